// round 4
// baseline (speedup 1.0000x reference)
#include <cuda_runtime.h>

#define BB 256
#define AA 128
#define DD 5
#define FATOM 256
#define FBOND 64
#define FTOT 320   // FATOM + FBOND
#define CC 256
#define NROWS (BB * AA)
#define TILE_M 16
#define TILES_X 80
#define CF 32                 // f-rows per W chunk
#define NCHUNK (FTOT / CF)    // 10

// Scratch (no device allocation allowed anywhere).
__device__ int g_count[DD];
__device__ int g_rows[DD * NROWS];

// ---------------- packed f32x2 helpers ----------------
__device__ __forceinline__ unsigned long long pack2(float lo, float hi) {
    unsigned long long r;
    asm("mov.b64 %0, {%1, %2};" : "=l"(r) : "f"(lo), "f"(hi));
    return r;
}
__device__ __forceinline__ void unpack2(unsigned long long v, float& lo, float& hi) {
    asm("mov.b64 {%0, %1}, %2;" : "=f"(lo), "=f"(hi) : "l"(v));
}
__device__ __forceinline__ unsigned long long fma2(unsigned long long a,
                                                   unsigned long long b,
                                                   unsigned long long c) {
    unsigned long long d;
    asm("fma.rn.f32x2 %0, %1, %2, %3;" : "=l"(d) : "l"(a), "l"(b), "l"(c));
    return d;
}

// ---------------- cp.async helpers ----------------
__device__ __forceinline__ void cp_async16(void* smem_dst, const void* gmem_src) {
    unsigned sa = (unsigned)__cvta_generic_to_shared(smem_dst);
    asm volatile("cp.async.cg.shared.global [%0], [%1], 16;\n"
                 :: "r"(sa), "l"(gmem_src) : "memory");
}
__device__ __forceinline__ void cp_commit() {
    asm volatile("cp.async.commit_group;\n" ::: "memory");
}
__device__ __forceinline__ void cp_wait1() {
    asm volatile("cp.async.wait_group 1;\n" ::: "memory");
}

// Kernel A (fused): per-row degree; deg==5 rows -> zero output row
// (mask one-hot over 0..4 is all-zero); deg<5 rows -> append to deg-list.
// Block = 256 threads = 8 warps; each warp handles 4 rows; grid 1024.
// Append order varies but each row is handled exactly once -> deterministic.
__global__ void __launch_bounds__(256) classify_zero_kernel(
    const int* __restrict__ edges, float4* __restrict__ out4)
{
    const int wid  = threadIdx.x >> 5;
    const int lane = threadIdx.x & 31;
    const int rbase = blockIdx.x * 32 + wid * 4;
    const float4 z = make_float4(0.f, 0.f, 0.f, 0.f);

#pragma unroll
    for (int i = 0; i < 4; i++) {
        const int row = rbase + i;
        int e = -1;
        if (lane < DD) e = edges[row * DD + lane];
        unsigned m = __ballot_sync(0xffffffffu, (lane < DD) && (e >= 0));
        int deg = __popc(m);
        if (deg == DD) {
            float4* o = out4 + row * (CC / 4);
            o[lane] = z;
            o[lane + 32] = z;
        } else if (lane == 0) {
            int pos = atomicAdd(&g_count[deg], 1);
            g_rows[deg * NROWS + pos] = row;
        }
    }
}

// Kernel B: per-deg grouped GEMM with double-buffered cp.async W staging.
//   feat[row] = [atoms[row] + sum_{e>=0} atoms[b,e]  |  sum_d bonds[row,d,:]]
//   out[row]  = relu(feat @ W[deg] + bias[deg])
// Block 256 threads; tile = 16 rows x 256 cols; thread = (col-pair, row-group
// of 8); inner product via packed fma.rn.f32x2 reading W from smem.
__global__ void __launch_bounds__(256) gemm_kernel(
    const float4* __restrict__ atoms4, const float4* __restrict__ bonds4,
    const int* __restrict__ edges, const float* __restrict__ W,
    const float* __restrict__ bias, float* __restrict__ out)
{
    __shared__ float feat[TILE_M][FTOT];       // 20 KB
    __shared__ float Wbuf[2][CF * CC];         // 2 x 32 KB

    const int deg = blockIdx.y;
    const int count = g_count[deg];
    if (count == 0) return;

    const int tid  = threadIdx.x;
    const int wid  = tid >> 5;
    const int lane = tid & 31;
    const int cp   = tid & 127;   // cols 2cp, 2cp+1
    const int rg   = tid >> 7;    // rows rg*8 .. rg*8+7
    const float* Wd = W + deg * FTOT * CC;
    const unsigned long long bv2 =
        *reinterpret_cast<const unsigned long long*>(&bias[deg * CC + 2 * cp]);

    for (int tile = blockIdx.x; tile * TILE_M < count; tile += gridDim.x) {
        const int base  = tile * TILE_M;
        const int nrows = min(TILE_M, count - base);

        __syncthreads();  // prior-iteration feat/Wbuf readers done

        // ---- Prefetch W chunks 0 and 1 (independent of feat) ----
#pragma unroll
        for (int c = 0; c < 2; c++) {
            const float4* src = reinterpret_cast<const float4*>(Wd + c * CF * CC);
#pragma unroll
            for (int i = 0; i < (CF * CC / 4) / 256; i++)   // 8 per thread
                cp_async16(&Wbuf[c][(tid + 256 * i) * 4], &src[tid + 256 * i]);
            cp_commit();
        }

        // ---- Feat build: warp 'wid' builds rows wid and wid+8 ----
#pragma unroll
        for (int rr = 0; rr < 2; rr++) {
            const int r = wid + rr * 8;
            if (r < nrows) {
                const int row   = g_rows[deg * NROWS + base + r];
                const int bbase = (row >> 7) << 7;  // b * AA
                int e[DD];
#pragma unroll
                for (int d = 0; d < DD; d++) e[d] = edges[row * DD + d];
#pragma unroll
                for (int k = 0; k < 2; k++) {
                    const int f4 = lane + 32 * k;
                    float4 v = atoms4[row * 64 + f4];
#pragma unroll
                    for (int d = 0; d < DD; d++) {
                        if (e[d] >= 0) {
                            float4 nv = atoms4[(bbase + e[d]) * 64 + f4];
                            v.x += nv.x; v.y += nv.y; v.z += nv.z; v.w += nv.w;
                        }
                    }
                    *reinterpret_cast<float4*>(&feat[r][f4 * 4]) = v;
                }
                if (lane < 16) {
                    float4 s = make_float4(0.f, 0.f, 0.f, 0.f);
#pragma unroll
                    for (int d = 0; d < DD; d++) {
                        float4 bvv = bonds4[(row * DD + d) * 16 + lane];
                        s.x += bvv.x; s.y += bvv.y; s.z += bvv.z; s.w += bvv.w;
                    }
                    *reinterpret_cast<float4*>(&feat[r][FATOM + lane * 4]) = s;
                }
            }
        }

        // ---- Main pipeline over W chunks ----
        unsigned long long acc[8];
#pragma unroll
        for (int r = 0; r < 8; r++) acc[r] = bv2;

        for (int c = 0; c < NCHUNK; c++) {
            cp_wait1();          // chunk c landed (<=1 group outstanding)
            __syncthreads();     // all threads' portions visible + feat ready (c==0)

            const float* Ws = Wbuf[c & 1];
            const int fb = c * CF;
#pragma unroll
            for (int f = 0; f < CF; f += 4) {
                unsigned long long w0 = *reinterpret_cast<const unsigned long long*>(
                    &Ws[(f + 0) * CC + 2 * cp]);
                unsigned long long w1 = *reinterpret_cast<const unsigned long long*>(
                    &Ws[(f + 1) * CC + 2 * cp]);
                unsigned long long w2 = *reinterpret_cast<const unsigned long long*>(
                    &Ws[(f + 2) * CC + 2 * cp]);
                unsigned long long w3 = *reinterpret_cast<const unsigned long long*>(
                    &Ws[(f + 3) * CC + 2 * cp]);
#pragma unroll
                for (int r = 0; r < 8; r++) {
                    const float4 fv = *reinterpret_cast<const float4*>(
                        &feat[rg * 8 + r][fb + f]);
                    acc[r] = fma2(pack2(fv.x, fv.x), w0, acc[r]);
                    acc[r] = fma2(pack2(fv.y, fv.y), w1, acc[r]);
                    acc[r] = fma2(pack2(fv.z, fv.z), w2, acc[r]);
                    acc[r] = fma2(pack2(fv.w, fv.w), w3, acc[r]);
                }
            }
            __syncthreads();     // everyone done reading Wbuf[c&1]
            if (c + 2 < NCHUNK) {
                const float4* src = reinterpret_cast<const float4*>(
                    Wd + (c + 2) * CF * CC);
#pragma unroll
                for (int i = 0; i < (CF * CC / 4) / 256; i++)
                    cp_async16(&Wbuf[c & 1][(tid + 256 * i) * 4], &src[tid + 256 * i]);
            }
            cp_commit();         // commit (possibly empty) to keep group count in step
        }

        // ---- Epilogue: relu + scatter ----
#pragma unroll
        for (int r = 0; r < 8; r++) {
            const int ri = rg * 8 + r;
            if (ri < nrows) {
                const int row = g_rows[deg * NROWS + base + ri];
                float lo, hi;
                unpack2(acc[r], lo, hi);
                float2 o = make_float2(fmaxf(lo, 0.f), fmaxf(hi, 0.f));
                *reinterpret_cast<float2*>(&out[row * CC + 2 * cp]) = o;
            }
        }
    }
}

extern "C" void kernel_launch(void* const* d_in, const int* in_sizes, int n_in,
                              void* d_out, int out_size) {
    const float* atoms = (const float*)d_in[0];   // (B, A, FA) f32
    const float* bonds = (const float*)d_in[1];   // (B, A, D, FB) f32
    const int*   edges = (const int*)d_in[2];     // (B, A, D) i32
    const float* W     = (const float*)d_in[3];   // (D, FA+FB, C) f32
    const float* bias  = (const float*)d_in[4];   // (D, C) f32
    float* out = (float*)d_out;                   // (B, A, C) f32

    // Reset compaction counters (memset node; no allocation).
    void* cnt_addr = nullptr;
    cudaGetSymbolAddress(&cnt_addr, g_count);
    cudaMemsetAsync(cnt_addr, 0, DD * sizeof(int));

    classify_zero_kernel<<<NROWS / 32, 256>>>(edges, (float4*)out);
    gemm_kernel<<<dim3(TILES_X, DD), 256>>>((const float4*)atoms,
                                            (const float4*)bonds,
                                            edges, W, bias, out);
}